// round 5
// baseline (speedup 1.0000x reference)
#include <cuda_runtime.h>
#include <cstdint>

// RipsH1 edge-length gather — pair-cooperative, U=2, occupancy-tuned.
//
// Flat distance list, D = e0 + 2*e1:
//   t <  e0 : (ia, ib) = verts0 row t
//   t >= e0 : (ia, ib) = ((int2*)verts1)[t - e0]
//   out[t]  = || pts[ia] - pts[ib] ||      (8-dim)
//
// - 2 lanes per distance (lane h owns float4 half h of each point; halves of a
//   point share one 32B sector -> 1 L1 wavefront per point).
// - U=2 distances per lane-pair: per-warp gather requests (128) already exceed
//   the ~55/warp outstanding-LDG cap, so keep regs low (-> 2048 thr/SM) rather
//   than deepening per-thread MLP.
// - Index loads use __ldcg and stores __stcg (L1-bypass): the 33MB index + 17MB
//   output streams have zero reuse; L1 stays a dedicated cache for the 2MB
//   points table (reused ~63x per point).

static constexpr int DIM_F4   = 2;      // 8 floats = 2 float4
static constexpr int IDX_MASK = 0xFFFF; // N_POINTS = 65536
static constexpr int U        = 2;      // distances per lane-pair
static constexpr int DIST_PER_WARP = 16 * U;  // 32

__device__ __forceinline__ int2 ldcg_int2(const int2* p) {
    int2 r;
    asm volatile("ld.global.cg.v2.s32 {%0, %1}, [%2];"
                 : "=r"(r.x), "=r"(r.y) : "l"(p));
    return r;
}

__device__ __forceinline__ void stcg_f32(float* p, float v) {
    asm volatile("st.global.cg.f32 [%0], %1;" :: "l"(p), "f"(v));
}

__global__ __launch_bounds__(256, 8)
void rips_pair_u2_kernel(const float4* __restrict__ pts,
                         const int2* __restrict__ v0,   // e0 rows of 2 i32
                         const int2* __restrict__ v1p,  // verts1 as 2*e1 int2 pairs
                         float* __restrict__ out,
                         int e0, int total) {           // total = e0 + 2*e1
    const int gtid  = blockIdx.x * blockDim.x + threadIdx.x;
    const int warp  = gtid >> 5;
    const int lane  = gtid & 31;
    const int pair  = lane >> 1;   // 0..15
    const int h     = lane & 1;    // float4 half owned by this lane

    const int base = warp * DIST_PER_WARP + pair;

    // ---- phase 1: index loads (L1-bypass) ----
    int t[U], ia[U], ib[U];
    bool valid[U];
#pragma unroll
    for (int u = 0; u < U; u++) {
        int tt = base + u * 16;
        valid[u] = (tt < total);
        tt = valid[u] ? tt : (total - 1);      // clamp -> safe, converged
        t[u] = tt;
        const int2 p = (tt < e0) ? ldcg_int2(v0 + tt)
                                 : ldcg_int2(v1p + (tt - e0));
        ia[u] = p.x & IDX_MASK;
        ib[u] = p.y & IDX_MASK;
    }

    // ---- phase 2: gathers (batched, L1-cached) ----
    float4 a[U], b[U];
#pragma unroll
    for (int u = 0; u < U; u++) {
        a[u] = __ldg(pts + ia[u] * DIM_F4 + h);
        b[u] = __ldg(pts + ib[u] * DIM_F4 + h);
    }

    // ---- phase 3: math + pair-combine + store (L1-bypass) ----
#pragma unroll
    for (int u = 0; u < U; u++) {
        float dx, s;
        dx = a[u].x - b[u].x; s = dx * dx;
        dx = a[u].y - b[u].y; s = fmaf(dx, dx, s);
        dx = a[u].z - b[u].z; s = fmaf(dx, dx, s);
        dx = a[u].w - b[u].w; s = fmaf(dx, dx, s);
        s += __shfl_xor_sync(0xFFFFFFFF, s, 1);
        if (valid[u] && h == 0)
            stcg_f32(out + t[u], sqrtf(s));
    }
}

extern "C" void kernel_launch(void* const* d_in, const int* in_sizes, int n_in,
                              void* d_out, int out_size) {
    const float4* pts = (const float4*)d_in[0];
    const int2*   v0  = (const int2*)d_in[1];
    const int2*   v1p = (const int2*)d_in[2];
    float*        out = (float*)d_out;

    const int e0 = in_sizes[1] / 2;          // verts0 rows
    const int e1 = in_sizes[2] / 4;          // verts1 rows
    const int total = e0 + 2 * e1;           // flat distance count

    const int nwarps  = (total + DIST_PER_WARP - 1) / DIST_PER_WARP;
    const int threads = 256;
    const int blocks  = (nwarps * 32 + threads - 1) / threads;
    rips_pair_u2_kernel<<<blocks, threads>>>(pts, v0, v1p, out, e0, total);
}